// round 11
// baseline (speedup 1.0000x reference)
#include <cuda_runtime.h>
#include <cuda_bf16.h>
#include <cuda_fp16.h>
#include <cstdint>

// Problem dims
#define BV   64
#define TT   500
#define FIN  1250
#define KP   1280          // FIN padded
#define HH   512
#define OO   2
#define MM   (BV * TT)     // 32000

// Neuron constants
#define DSYN  0.9048374180359595f
#define DREF  0.36787944117144233f
#define THETA 10.0f

// Scratch (device globals: allocation-free rule)
__device__ __align__(16) unsigned char  g_w1f8[(size_t)HH * KP]; // 640 KB e4m3
__device__ __align__(16) __half          g_u1 [(size_t)MM * HH]; // 32 MB fp16
__device__ __align__(16) __nv_bfloat16  g_s1 [(size_t)MM * HH]; // 32 MB
__device__ __align__(16) float           g_u2 [(size_t)MM * OO]; // 256 KB

// ---------------------------------------------------------------------------
// PTX helpers
// ---------------------------------------------------------------------------
__device__ __forceinline__ void ldsm_x4(uint32_t &r0, uint32_t &r1,
                                        uint32_t &r2, uint32_t &r3,
                                        uint32_t addr)
{
    asm volatile("ldmatrix.sync.aligned.m8n8.x4.shared.b16 {%0,%1,%2,%3}, [%4];"
                 : "=r"(r0), "=r"(r1), "=r"(r2), "=r"(r3) : "r"(addr));
}

// fp8 e4m3 MMA, k=32 per instruction, fp32 accum
__device__ __forceinline__ void mma16832_f8(float* c, const uint32_t* a,
                                            const uint32_t b0, const uint32_t b1)
{
    asm volatile(
        "mma.sync.aligned.m16n8k32.row.col.f32.e4m3.e4m3.f32 "
        "{%0,%1,%2,%3}, {%4,%5,%6,%7}, {%8,%9}, {%0,%1,%2,%3};"
        : "+f"(c[0]), "+f"(c[1]), "+f"(c[2]), "+f"(c[3])
        : "r"(a[0]), "r"(a[1]), "r"(a[2]), "r"(a[3]), "r"(b0), "r"(b1));
}

// pack 4 fp32 -> 4 e4m3 bytes (k-ascending byte order)
__device__ __forceinline__ uint32_t cvt4_e4m3(float f0, float f1,
                                              float f2, float f3)
{
    uint32_t pk;
    asm("{ .reg .b16 lo, hi;\n\t"
        "cvt.rn.satfinite.e4m3x2.f32 lo, %2, %1;\n\t"
        "cvt.rn.satfinite.e4m3x2.f32 hi, %4, %3;\n\t"
        "mov.b32 %0, {lo, hi}; }"
        : "=r"(pk) : "f"(f0), "f"(f1), "f"(f2), "f"(f3));
    return pk;
}

__device__ __forceinline__ void cp_async16(uint32_t smem_addr, const void* gptr)
{
    asm volatile("cp.async.cg.shared.global [%0], [%1], 16;"
                 :: "r"(smem_addr), "l"(gptr));
}
__device__ __forceinline__ void cp_commit()
{
    asm volatile("cp.async.commit_group;");
}
__device__ __forceinline__ void cp_wait0()
{
    asm volatile("cp.async.wait_group 0;");
}

// ---------------------------------------------------------------------------
// K0: W1 fp32 -> e4m3, pad K 1250 -> 1280 (640 KB; L2-resident)
// ---------------------------------------------------------------------------
__global__ __launch_bounds__(256) void cvt_w1_kernel(
    const float* __restrict__ W, unsigned char* __restrict__ Wf)
{
    long i = (long)blockIdx.x * blockDim.x + threadIdx.x;
    if (i >= (long)HH * KP) return;
    int  k = (int)(i % KP);
    long h = i / KP;
    float v = (k < FIN) ? W[h * FIN + k] : 0.0f;
    uint32_t pk = cvt4_e4m3(v, 0.0f, 0.0f, 0.0f);
    Wf[i] = (unsigned char)(pk & 0xFF);
}

// ---------------------------------------------------------------------------
// K1: U1[m,h] = sum_k X[m,k] * W1[h,k]   (e4m3 MMA k32, fp32 acc, fp16 out)
// BM=64, BN=256, BK=128 fp8, occ 2, NKCH=10. 8 warps 2(m) x 4(n),
// warp tile 32x64. A: fp32 LDG -> cvt e4m3 -> STS, one chunk ahead.
// B: cp.async double buffer. Rows: 128B data + 16B pad = 144B pitch
// (identical byte addressing to the b16 version; 2 fp8 == 1 b16 unit).
// ---------------------------------------------------------------------------
#define BM 64
#define BN 256
#define BKF 128                    // fp8 elements per chunk
#define ROWB 144                   // bytes per padded row
#define ABUFB (BM * ROWB)          // 9216
#define BBUFB (BN * ROWB)          // 36864
#define SMEM_GEMM (2 * ABUFB + 2 * BBUFB)   // 92160
#define NKCH (KP / BKF)            // 10

__global__ __launch_bounds__(256, 2) void gemm1_mma_kernel(
    const float* __restrict__ X,
    const unsigned char* __restrict__ Wf,
    __half* __restrict__ U)
{
    extern __shared__ __align__(16) char smem[];
    char* As = smem;
    char* Bs = smem + 2 * ABUFB;

    const int tid  = threadIdx.x;
    const int warp = tid >> 5;
    const int lane = tid & 31;
    const int wm   = warp >> 2;            // 0..1 -> m off wm*32
    const int wn   = warp & 3;             // 0..3 -> n off wn*64
    const int bm   = blockIdx.y * BM;
    const int bn   = blockIdx.x * BN;

    float acc[2][8][4];
#pragma unroll
    for (int i = 0; i < 2; i++)
#pragma unroll
        for (int j = 0; j < 8; j++)
#pragma unroll
            for (int q = 0; q < 4; q++) acc[i][j][q] = 0.0f;

    const uint32_t asB = (uint32_t)__cvta_generic_to_shared(As);
    const uint32_t bsB = (uint32_t)__cvta_generic_to_shared(Bs);

    // A: 64 rows x 128 floats per chunk; thread t: row=t>>2, seg=(t&3)*32 floats
    const int aRow = tid >> 2;
    const int aSeg = (tid & 3) * 32;       // float offset within chunk
    // B: 256 rows x 128B = 2048 x16B units, 8/thread: row=(tid>>3)+j*32, g=tid&7
    const int bRowL = tid >> 3;
    const int bG    = tid & 7;

    const float* Xr = X + (size_t)(bm + aRow) * FIN + aSeg;

    uint32_t pk[8];                        // 32 e4m3 bytes packed

    // ---- preload chunk 0
    {
#pragma unroll
        for (int j = 0; j < 8; j++) {
            float2 v0 = *(const float2*)(Xr + j * 4);
            float2 v1 = *(const float2*)(Xr + j * 4 + 2);
            pk[j] = cvt4_e4m3(v0.x, v0.y, v1.x, v1.y);
        }
        uint4* dst = (uint4*)(As + aRow * ROWB + aSeg);
        dst[0] = make_uint4(pk[0], pk[1], pk[2], pk[3]);
        dst[1] = make_uint4(pk[4], pk[5], pk[6], pk[7]);
#pragma unroll
        for (int j = 0; j < 8; j++) {
            int row = bRowL + j * 32;
            cp_async16(bsB + (uint32_t)(row * ROWB + bG * 16),
                       Wf + (size_t)(bn + row) * KP + bG * 16);
        }
        cp_commit();
    }

    // ldmatrix lane addressing (byte offsets; identical to b16 scheme)
    const uint32_t aRowOff = (uint32_t)(wm * 32 + (lane & 15));
    const uint32_t aColOff = (uint32_t)((lane >> 4) * 16);
    const uint32_t bRowOff = (uint32_t)(wn * 64 + ((lane >> 4) & 1) * 8 + (lane & 7));
    const uint32_t bColOff = (uint32_t)(((lane >> 3) & 1) * 16);

    for (int kt = 0; kt < NKCH; kt++) {
        cp_wait0();
        __syncthreads();                   // buffer kt&1 ready; nb free

        const int nb = (kt + 1) & 1;
        const bool more = (kt + 1 < NKCH);

        if (more) {
            const int kn = (kt + 1) * BKF;
            if (kt + 1 < NKCH - 1) {
#pragma unroll
                for (int j = 0; j < 8; j++) {
                    float2 v0 = *(const float2*)(Xr + kn + j * 4);
                    float2 v1 = *(const float2*)(Xr + kn + j * 4 + 2);
                    pk[j] = cvt4_e4m3(v0.x, v0.y, v1.x, v1.y);
                }
            } else {                        // last chunk: k 1152..1279, guard
#pragma unroll
                for (int j = 0; j < 8; j++) {
                    int k0 = kn + aSeg + j * 4;
                    float2 v0 = (k0     + 1 < FIN) ? *(const float2*)(Xr + kn + j * 4)
                                                   : make_float2(0.0f, 0.0f);
                    float2 v1 = (k0 + 2 + 1 < FIN) ? *(const float2*)(Xr + kn + j * 4 + 2)
                                                   : make_float2(0.0f, 0.0f);
                    pk[j] = cvt4_e4m3(v0.x, v0.y, v1.x, v1.y);
                }
            }
#pragma unroll
            for (int j = 0; j < 8; j++) {
                int row = bRowL + j * 32;
                cp_async16(bsB + (uint32_t)(nb * BBUFB + row * ROWB + bG * 16),
                           Wf + (size_t)(bn + row) * KP + kn + bG * 16);
            }
            cp_commit();
        } else {
            cp_commit();
        }

        const uint32_t aBase = asB + (uint32_t)((kt & 1) * ABUFB);
        const uint32_t bBase = bsB + (uint32_t)((kt & 1) * BBUFB);

#pragma unroll
        for (int ks = 0; ks < 4; ks++) {   // 4 x k32 = 128 fp8
            uint32_t a[2][4];
#pragma unroll
            for (int mt = 0; mt < 2; mt++) {
                uint32_t addr = aBase + (aRowOff + mt * 16) * ROWB
                                      + ks * 32 + aColOff;
                ldsm_x4(a[mt][0], a[mt][1], a[mt][2], a[mt][3], addr);
            }
            uint32_t b[4][4];
#pragma unroll
            for (int p = 0; p < 4; p++) {
                uint32_t addr = bBase + (bRowOff + p * 16) * ROWB
                                      + ks * 32 + bColOff;
                ldsm_x4(b[p][0], b[p][1], b[p][2], b[p][3], addr);
            }
#pragma unroll
            for (int mt = 0; mt < 2; mt++)
#pragma unroll
                for (int nt = 0; nt < 8; nt++)
                    mma16832_f8(acc[mt][nt], a[mt],
                                b[nt >> 1][(nt & 1) * 2],
                                b[nt >> 1][(nt & 1) * 2 + 1]);
        }

        if (more) {
            uint4* dst = (uint4*)(As + nb * ABUFB + aRow * ROWB + aSeg);
            dst[0] = make_uint4(pk[0], pk[1], pk[2], pk[3]);
            dst[1] = make_uint4(pk[4], pk[5], pk[6], pk[7]);
        }
    }

    // epilogue: fp16 stores
    const int cr = lane >> 2;
    const int cc = (lane & 3) * 2;
#pragma unroll
    for (int mt = 0; mt < 2; mt++) {
#pragma unroll
        for (int nt = 0; nt < 8; nt++) {
            int row0 = bm + wm * 32 + mt * 16 + cr;
            int col  = bn + wn * 64 + nt * 8 + cc;
            __half2 v01 = __floats2half2_rn(acc[mt][nt][0], acc[mt][nt][1]);
            __half2 v23 = __floats2half2_rn(acc[mt][nt][2], acc[mt][nt][3]);
            *(__half2*)(U + (size_t)row0 * HH + col)       = v01;
            *(__half2*)(U + (size_t)(row0 + 8) * HH + col) = v23;
        }
    }
}

// ---------------------------------------------------------------------------
// K2: fused PSP + spike scan, layer 1 (fp16 in, bf16 out).
// One thread per (b,h) chain, two-named-buffer prefetch, static indices.
// ---------------------------------------------------------------------------
#define SCH 10
__global__ __launch_bounds__(128) void scan1_kernel(
    const __half* __restrict__ U1, __nv_bfloat16* __restrict__ S1)
{
    const int b = blockIdx.x;
    const int h = blockIdx.y * 128 + threadIdx.x;
    const __half*        up = U1 + (size_t)b * TT * HH + h;
    __nv_bfloat16*       sp = S1 + (size_t)b * TT * HH + h;

    float b0[SCH], b1[SCH];
#pragma unroll
    for (int j = 0; j < SCH; j++) b0[j] = __half2float(up[(size_t)j * HH]);

    float p = 0.0f, r = 0.0f;
    const int NC = TT / SCH;             // 50 (even)
    for (int c = 0; c < NC; c += 2) {
        {
            const __half* nx = up + (size_t)(c + 1) * SCH * HH;
#pragma unroll
            for (int j = 0; j < SCH; j++) b1[j] = __half2float(nx[(size_t)j * HH]);
        }
        {
            __nv_bfloat16* so = sp + (size_t)c * SCH * HH;
#pragma unroll
            for (int j = 0; j < SCH; j++) {
                p = DSYN * p + b0[j];
                float v = p + r;
                float s = (v >= THETA) ? 1.0f : 0.0f;
                r = DREF * (r - 2.0f * THETA * s);
                so[(size_t)j * HH] = __float2bfloat16(s);
            }
        }
        if (c + 2 < NC) {
            const __half* nx = up + (size_t)(c + 2) * SCH * HH;
#pragma unroll
            for (int j = 0; j < SCH; j++) b0[j] = __half2float(nx[(size_t)j * HH]);
        }
        {
            __nv_bfloat16* so = sp + (size_t)(c + 1) * SCH * HH;
#pragma unroll
            for (int j = 0; j < SCH; j++) {
                p = DSYN * p + b1[j];
                float v = p + r;
                float s = (v >= THETA) ? 1.0f : 0.0f;
                r = DREF * (r - 2.0f * THETA * s);
                so[(size_t)j * HH] = __float2bfloat16(s);
            }
        }
    }
}

// ---------------------------------------------------------------------------
// K3: U2[m,o] = sum_h S1[m,h] * W2[o,h]. Warp per row (proven pattern):
// lane-strided h = lane + 32i -> conflict-free smem W2, coalesced s1.
// ---------------------------------------------------------------------------
__global__ __launch_bounds__(256) void gemm2_kernel(
    const __nv_bfloat16* __restrict__ S1, const float* __restrict__ W2,
    float* __restrict__ U2)
{
    __shared__ float w2s[OO * HH];
    for (int i = threadIdx.x; i < OO * HH; i += blockDim.x) w2s[i] = W2[i];
    __syncthreads();

    const int gwarp = (blockIdx.x * blockDim.x + threadIdx.x) >> 5;
    const int lane  = threadIdx.x & 31;
    if (gwarp >= MM) return;

    const __nv_bfloat16* s = S1 + (size_t)gwarp * HH;
    float a0 = 0.0f, a1 = 0.0f;
#pragma unroll
    for (int h = lane; h < HH; h += 32) {
        float sv = __bfloat162float(s[h]);
        a0 += sv * w2s[h];
        a1 += sv * w2s[HH + h];
    }
#pragma unroll
    for (int off = 16; off > 0; off >>= 1) {
        a0 += __shfl_xor_sync(0xFFFFFFFFu, a0, off);
        a1 += __shfl_xor_sync(0xFFFFFFFFu, a1, off);
    }
    if (lane == 0) {
        U2[(size_t)gwarp * OO + 0] = a0;
        U2[(size_t)gwarp * OO + 1] = a1;
    }
}

// ---------------------------------------------------------------------------
// K4: scan layer 2. Explicit two-named-buffer pipeline.
// ---------------------------------------------------------------------------
#define SC2 20
__global__ __launch_bounds__(128) void scan2_kernel(
    const float* __restrict__ U2, float* __restrict__ out)
{
    const int i = threadIdx.x;
    const int b = i >> 1;
    const int o = i & 1;
    const float* up = U2  + (size_t)b * TT * OO + o;
    float*       op = out + (size_t)b * TT * OO + o;

    float b0[SC2], b1[SC2];
#pragma unroll
    for (int j = 0; j < SC2; j++) b0[j] = up[(size_t)j * OO];

    float p = 0.0f, r = 0.0f;
    const int NC = TT / SC2;             // 25 (odd)
    for (int c = 0; c < NC; c += 2) {
        if (c + 1 < NC) {
            const float* nx = up + (size_t)(c + 1) * SC2 * OO;
#pragma unroll
            for (int j = 0; j < SC2; j++) b1[j] = nx[(size_t)j * OO];
        }
        {
            float* oo = op + (size_t)c * SC2 * OO;
#pragma unroll
            for (int j = 0; j < SC2; j++) {
                p = DSYN * p + b0[j];
                float v = p + r;
                float s = (v >= THETA) ? 1.0f : 0.0f;
                r = DREF * (r - 2.0f * THETA * s);
                oo[(size_t)j * OO] = s;
            }
        }
        if (c + 2 < NC) {
            const float* nx = up + (size_t)(c + 2) * SC2 * OO;
#pragma unroll
            for (int j = 0; j < SC2; j++) b0[j] = nx[(size_t)j * OO];
        }
        if (c + 1 < NC) {
            float* oo = op + (size_t)(c + 1) * SC2 * OO;
#pragma unroll
            for (int j = 0; j < SC2; j++) {
                p = DSYN * p + b1[j];
                float v = p + r;
                float s = (v >= THETA) ? 1.0f : 0.0f;
                r = DREF * (r - 2.0f * THETA * s);
                oo[(size_t)j * OO] = s;
            }
        }
    }
}

// ---------------------------------------------------------------------------
extern "C" void kernel_launch(void* const* d_in, const int* in_sizes, int n_in,
                              void* d_out, int out_size)
{
    const float* x  = (const float*)d_in[0];   // (64, 500, 1250)
    const float* W1 = (const float*)d_in[1];   // (512, 1250)
    const float* W2 = (const float*)d_in[2];   // (2, 512)
    float* out = (float*)d_out;                // (64, 500, 2)

    unsigned char* w1f; cudaGetSymbolAddress((void**)&w1f, g_w1f8);
    __half*        u1;  cudaGetSymbolAddress((void**)&u1,  g_u1);
    __nv_bfloat16* s1;  cudaGetSymbolAddress((void**)&s1,  g_s1);
    float*         u2;  cudaGetSymbolAddress((void**)&u2,  g_u2);

    {
        long n = (long)HH * KP;
        cvt_w1_kernel<<<(unsigned)((n + 255) / 256), 256>>>(W1, w1f);
    }

    cudaFuncSetAttribute(gemm1_mma_kernel,
                         cudaFuncAttributeMaxDynamicSharedMemorySize, SMEM_GEMM);
    dim3 g1(HH / BN, MM / BM);                // (2, 500)
    gemm1_mma_kernel<<<g1, 256, SMEM_GEMM>>>(x, w1f, u1);

    dim3 g2(BV, HH / 128);                    // (64, 4)
    scan1_kernel<<<g2, 128>>>(u1, s1);

    gemm2_kernel<<<(MM * 32 + 255) / 256, 256>>>(s1, W2, u2);

    scan2_kernel<<<1, 128>>>(u2, out);
}

// round 12
// speedup vs baseline: 1.3918x; 1.3918x over previous
#include <cuda_runtime.h>
#include <cuda_bf16.h>
#include <cuda_fp16.h>
#include <cstdint>

// Problem dims
#define BV   64
#define TT   500
#define FIN  1250
#define KP   1280          // FIN padded for B
#define HH   512
#define OO   2
#define MM   (BV * TT)     // 32000

// Neuron constants
#define DSYN  0.9048374180359595f
#define DREF  0.36787944117144233f
#define THETA 10.0f

// Scratch (device globals: allocation-free rule)
__device__ __align__(16) __half          g_w1h[(size_t)HH * KP];  // 1.3 MB
__device__ __align__(16) __half          g_u1 [(size_t)MM * HH];  // 32 MB (fp16)
__device__ __align__(16) __nv_bfloat16  g_s1 [(size_t)MM * HH];  // 32 MB
__device__ __align__(16) float           g_u2 [(size_t)MM * OO]; // 256 KB

// ---------------------------------------------------------------------------
// PTX helpers
// ---------------------------------------------------------------------------
__device__ __forceinline__ void ldsm_x4(uint32_t &r0, uint32_t &r1,
                                        uint32_t &r2, uint32_t &r3,
                                        uint32_t addr)
{
    asm volatile("ldmatrix.sync.aligned.m8n8.x4.shared.b16 {%0,%1,%2,%3}, [%4];"
                 : "=r"(r0), "=r"(r1), "=r"(r2), "=r"(r3) : "r"(addr));
}

// fp16-accumulator MMA: D(2 regs) = A(4) * B(2) + D
__device__ __forceinline__ void mma16816_f16(uint32_t* c, const uint32_t* a,
                                             const uint32_t b0, const uint32_t b1)
{
    asm volatile(
        "mma.sync.aligned.m16n8k16.row.col.f16.f16.f16.f16 "
        "{%0,%1}, {%2,%3,%4,%5}, {%6,%7}, {%0,%1};"
        : "+r"(c[0]), "+r"(c[1])
        : "r"(a[0]), "r"(a[1]), "r"(a[2]), "r"(a[3]), "r"(b0), "r"(b1));
}

__device__ __forceinline__ void cp_async16(uint32_t smem_addr, const void* gptr)
{
    asm volatile("cp.async.cg.shared.global [%0], [%1], 16;"
                 :: "r"(smem_addr), "l"(gptr));
}
__device__ __forceinline__ void cp_commit()
{
    asm volatile("cp.async.commit_group;");
}
__device__ __forceinline__ void cp_wait0()
{
    asm volatile("cp.async.wait_group 0;");
}

// ---------------------------------------------------------------------------
// K0: W1 fp32 -> fp16, pad K 1250 -> 1280 (L2-resident thereafter)
// ---------------------------------------------------------------------------
__global__ __launch_bounds__(256) void cvt_w1_kernel(
    const float* __restrict__ W, __half* __restrict__ Wh)
{
    long i = (long)blockIdx.x * blockDim.x + threadIdx.x;
    if (i >= (long)HH * KP) return;
    int  k = (int)(i % KP);
    long h = i / KP;
    float v = (k < FIN) ? W[h * FIN + k] : 0.0f;
    Wh[i] = __float2half(v);
}

// ---------------------------------------------------------------------------
// K1: U1[m,h] = sum_k X[m,k] * W1[h,k]   (fp16 HMMA, fp16 accum, fp16 out)
// R10-proven: BM=64, BN=256, BK=64, occ 2. 8 warps as 2(m) x 4(n),
// warp tile 32x64. A: fp32 LDG -> regs -> fp16 STS, one chunk ahead.
// B: cp.async dbl buffer. Rows padded to 72 halves (144B).
// ---------------------------------------------------------------------------
#define BM 64
#define BN 256
#define BK 64
#define LDA 72
#define ROWB (LDA * 2)             // 144 bytes/row
#define ABUFB (BM * ROWB)          // 9216
#define BBUFB (BN * ROWB)          // 36864
#define SMEM_GEMM (2 * ABUFB + 2 * BBUFB)   // 92160
#define NKCH (KP / BK)             // 20

__global__ __launch_bounds__(256, 2) void gemm1_mma_kernel(
    const float* __restrict__ X,
    const __half* __restrict__ Wh,
    __half* __restrict__ U)
{
    extern __shared__ __align__(16) char smem[];
    char* As = smem;
    char* Bs = smem + 2 * ABUFB;

    const int tid  = threadIdx.x;
    const int warp = tid >> 5;
    const int lane = tid & 31;
    const int wm   = warp >> 2;            // 0..1 -> m off wm*32
    const int wn   = warp & 3;             // 0..3 -> n off wn*64
    const int bm   = blockIdx.y * BM;
    const int bn   = blockIdx.x * BN;

    uint32_t acc[2][8][2];                 // fp16x2 accumulators
#pragma unroll
    for (int i = 0; i < 2; i++)
#pragma unroll
        for (int j = 0; j < 8; j++) {
            acc[i][j][0] = 0u;
            acc[i][j][1] = 0u;
        }

    const uint32_t asB = (uint32_t)__cvta_generic_to_shared(As);
    const uint32_t bsB = (uint32_t)__cvta_generic_to_shared(Bs);

    // A: 64 rows x 32 float2 = 2048 units, 8/thread. row=(tid>>5)+j*8, c2=tid&31
    const int aRowL = tid >> 5;
    const int aC2   = tid & 31;
    // B: 256 rows x 128B = 2048 x16B, 8/thread. row=(tid>>3)+j*32, g=tid&7
    const int bRowL = tid >> 3;
    const int bG    = tid & 7;

    const float* Xb = X + (size_t)bm * FIN;

    float2 pre[8];

    // ---- preload chunk 0
    {
#pragma unroll
        for (int j = 0; j < 8; j++) {
            int row = aRowL + j * 8;
            pre[j] = *(const float2*)(Xb + (size_t)row * FIN + aC2 * 2);
        }
#pragma unroll
        for (int j = 0; j < 8; j++) {
            int row = aRowL + j * 8;
            __half2 h2 = __float22half2_rn(pre[j]);
            *(__half2*)(As + row * ROWB + aC2 * 4) = h2;
        }
#pragma unroll
        for (int j = 0; j < 8; j++) {
            int row = bRowL + j * 32;
            cp_async16(bsB + (uint32_t)(row * ROWB + bG * 16),
                       Wh + (size_t)(bn + row) * KP + bG * 8);
        }
        cp_commit();
    }

    const uint32_t aRowOff = (uint32_t)(wm * 32 + (lane & 15));
    const uint32_t aColOff = (uint32_t)((lane >> 4) * 16);
    const uint32_t bRowOff = (uint32_t)(wn * 64 + ((lane >> 4) & 1) * 8 + (lane & 7));
    const uint32_t bColOff = (uint32_t)(((lane >> 3) & 1) * 16);

    for (int kt = 0; kt < NKCH; kt++) {
        cp_wait0();
        __syncthreads();                   // buffer kt&1 ready; nb free

        const int nb = (kt + 1) & 1;
        const bool more = (kt + 1 < NKCH);

        if (more) {
            const int kn = (kt + 1) * BK;
            if (kt + 1 < NKCH - 1) {
#pragma unroll
                for (int j = 0; j < 8; j++) {
                    int row = aRowL + j * 8;
                    pre[j] = *(const float2*)(Xb + (size_t)row * FIN + kn + aC2 * 2);
                }
            } else {                        // last chunk: k 1216..1279
#pragma unroll
                for (int j = 0; j < 8; j++) {
                    int row = aRowL + j * 8;
                    int k   = kn + aC2 * 2;
                    pre[j] = (k < FIN)
                        ? *(const float2*)(Xb + (size_t)row * FIN + k)
                        : make_float2(0.0f, 0.0f);
                }
            }
#pragma unroll
            for (int j = 0; j < 8; j++) {
                int row = bRowL + j * 32;
                cp_async16(bsB + (uint32_t)(nb * BBUFB + row * ROWB + bG * 16),
                           Wh + (size_t)(bn + row) * KP + kn + bG * 8);
            }
            cp_commit();
        } else {
            cp_commit();
        }

        const uint32_t aBase = asB + (uint32_t)((kt & 1) * ABUFB);
        const uint32_t bBase = bsB + (uint32_t)((kt & 1) * BBUFB);

#pragma unroll
        for (int ks = 0; ks < 4; ks++) {
            uint32_t a[2][4];
#pragma unroll
            for (int mt = 0; mt < 2; mt++) {
                uint32_t addr = aBase + (aRowOff + mt * 16) * ROWB
                                      + ks * 32 + aColOff;
                ldsm_x4(a[mt][0], a[mt][1], a[mt][2], a[mt][3], addr);
            }
            uint32_t b[4][4];
#pragma unroll
            for (int p = 0; p < 4; p++) {
                uint32_t addr = bBase + (bRowOff + p * 16) * ROWB
                                      + ks * 32 + bColOff;
                ldsm_x4(b[p][0], b[p][1], b[p][2], b[p][3], addr);
            }
#pragma unroll
            for (int mt = 0; mt < 2; mt++)
#pragma unroll
                for (int nt = 0; nt < 8; nt++)
                    mma16816_f16(acc[mt][nt], a[mt],
                                 b[nt >> 1][(nt & 1) * 2],
                                 b[nt >> 1][(nt & 1) * 2 + 1]);
        }

        if (more) {
#pragma unroll
            for (int j = 0; j < 8; j++) {
                int row = aRowL + j * 8;
                __half2 h2 = __float22half2_rn(pre[j]);
                *(__half2*)(As + nb * ABUFB + row * ROWB + aC2 * 4) = h2;
            }
        }
    }

    // epilogue: raw fp16x2 stores (frag reg0 -> row, reg1 -> row+8)
    const int cr = lane >> 2;
    const int cc = (lane & 3) * 2;
#pragma unroll
    for (int mt = 0; mt < 2; mt++) {
#pragma unroll
        for (int nt = 0; nt < 8; nt++) {
            int row0 = bm + wm * 32 + mt * 16 + cr;
            int col  = bn + wn * 64 + nt * 8 + cc;
            *(uint32_t*)(U + (size_t)row0 * HH + col)       = acc[mt][nt][0];
            *(uint32_t*)(U + (size_t)(row0 + 8) * HH + col) = acc[mt][nt][1];
        }
    }
}

// ---------------------------------------------------------------------------
// K2: fused PSP + spike scan, layer 1 (fp16 in, bf16 out).
// One thread per (b,h) chain, two-named-buffer prefetch, static indices.
// ---------------------------------------------------------------------------
#define SCH 10
__global__ __launch_bounds__(128) void scan1_kernel(
    const __half* __restrict__ U1, __nv_bfloat16* __restrict__ S1)
{
    const int b = blockIdx.x;
    const int h = blockIdx.y * 128 + threadIdx.x;
    const __half*        up = U1 + (size_t)b * TT * HH + h;
    __nv_bfloat16*       sp = S1 + (size_t)b * TT * HH + h;

    float b0[SCH], b1[SCH];
#pragma unroll
    for (int j = 0; j < SCH; j++) b0[j] = __half2float(up[(size_t)j * HH]);

    float p = 0.0f, r = 0.0f;
    const int NC = TT / SCH;             // 50 (even)
    for (int c = 0; c < NC; c += 2) {
        {
            const __half* nx = up + (size_t)(c + 1) * SCH * HH;
#pragma unroll
            for (int j = 0; j < SCH; j++) b1[j] = __half2float(nx[(size_t)j * HH]);
        }
        {
            __nv_bfloat16* so = sp + (size_t)c * SCH * HH;
#pragma unroll
            for (int j = 0; j < SCH; j++) {
                p = DSYN * p + b0[j];
                float v = p + r;
                float s = (v >= THETA) ? 1.0f : 0.0f;
                r = DREF * (r - 2.0f * THETA * s);
                so[(size_t)j * HH] = __float2bfloat16(s);
            }
        }
        if (c + 2 < NC) {
            const __half* nx = up + (size_t)(c + 2) * SCH * HH;
#pragma unroll
            for (int j = 0; j < SCH; j++) b0[j] = __half2float(nx[(size_t)j * HH]);
        }
        {
            __nv_bfloat16* so = sp + (size_t)(c + 1) * SCH * HH;
#pragma unroll
            for (int j = 0; j < SCH; j++) {
                p = DSYN * p + b1[j];
                float v = p + r;
                float s = (v >= THETA) ? 1.0f : 0.0f;
                r = DREF * (r - 2.0f * THETA * s);
                so[(size_t)j * HH] = __float2bfloat16(s);
            }
        }
    }
}

// ---------------------------------------------------------------------------
// K3: U2[m,o] = sum_h S1[m,h] * W2[o,h]. Warp per row; PAIRED loads:
// pair index h2 = lane + 32i (lane stride 4B in smem -> conflict-free,
// coalesced 128B/warp bf16x2 LDG on s1). W2 staged as packed bf16x2.
// ---------------------------------------------------------------------------
__global__ __launch_bounds__(256) void gemm2_kernel(
    const __nv_bfloat16* __restrict__ S1, const float* __restrict__ W2,
    float* __restrict__ U2)
{
    __shared__ uint32_t wp0[HH / 2];       // bf16x2 pairs, o=0
    __shared__ uint32_t wp1[HH / 2];       // bf16x2 pairs, o=1
    for (int i = threadIdx.x; i < HH / 2; i += blockDim.x) {
        __nv_bfloat162 p0 = __floats2bfloat162_rn(W2[i * 2],      W2[i * 2 + 1]);
        __nv_bfloat162 p1 = __floats2bfloat162_rn(W2[HH + i * 2], W2[HH + i * 2 + 1]);
        wp0[i] = *(const uint32_t*)&p0;
        wp1[i] = *(const uint32_t*)&p1;
    }
    __syncthreads();

    const int gwarp = (blockIdx.x * blockDim.x + threadIdx.x) >> 5;
    const int lane  = threadIdx.x & 31;
    if (gwarp >= MM) return;

    const uint32_t* s2 = (const uint32_t*)(S1 + (size_t)gwarp * HH);
    float a0 = 0.0f, a1 = 0.0f;
#pragma unroll
    for (int i = 0; i < HH / 64; i++) {    // 8 iterations
        const int h2 = lane + i * 32;
        uint32_t sp = s2[h2];
        float2 sv  = __bfloat1622float2(*(const __nv_bfloat162*)&sp);
        float2 w0v = __bfloat1622float2(*(const __nv_bfloat162*)&wp0[h2]);
        float2 w1v = __bfloat1622float2(*(const __nv_bfloat162*)&wp1[h2]);
        a0 += sv.x * w0v.x + sv.y * w0v.y;
        a1 += sv.x * w1v.x + sv.y * w1v.y;
    }
#pragma unroll
    for (int off = 16; off > 0; off >>= 1) {
        a0 += __shfl_xor_sync(0xFFFFFFFFu, a0, off);
        a1 += __shfl_xor_sync(0xFFFFFFFFu, a1, off);
    }
    if (lane == 0) {
        U2[(size_t)gwarp * OO + 0] = a0;
        U2[(size_t)gwarp * OO + 1] = a1;
    }
}

// ---------------------------------------------------------------------------
// K4: scan layer 2. Explicit two-named-buffer pipeline.
// ---------------------------------------------------------------------------
#define SC2 20
__global__ __launch_bounds__(128) void scan2_kernel(
    const float* __restrict__ U2, float* __restrict__ out)
{
    const int i = threadIdx.x;
    const int b = i >> 1;
    const int o = i & 1;
    const float* up = U2  + (size_t)b * TT * OO + o;
    float*       op = out + (size_t)b * TT * OO + o;

    float b0[SC2], b1[SC2];
#pragma unroll
    for (int j = 0; j < SC2; j++) b0[j] = up[(size_t)j * OO];

    float p = 0.0f, r = 0.0f;
    const int NC = TT / SC2;             // 25 (odd)
    for (int c = 0; c < NC; c += 2) {
        if (c + 1 < NC) {
            const float* nx = up + (size_t)(c + 1) * SC2 * OO;
#pragma unroll
            for (int j = 0; j < SC2; j++) b1[j] = nx[(size_t)j * OO];
        }
        {
            float* oo = op + (size_t)c * SC2 * OO;
#pragma unroll
            for (int j = 0; j < SC2; j++) {
                p = DSYN * p + b0[j];
                float v = p + r;
                float s = (v >= THETA) ? 1.0f : 0.0f;
                r = DREF * (r - 2.0f * THETA * s);
                oo[(size_t)j * OO] = s;
            }
        }
        if (c + 2 < NC) {
            const float* nx = up + (size_t)(c + 2) * SC2 * OO;
#pragma unroll
            for (int j = 0; j < SC2; j++) b0[j] = nx[(size_t)j * OO];
        }
        if (c + 1 < NC) {
            float* oo = op + (size_t)(c + 1) * SC2 * OO;
#pragma unroll
            for (int j = 0; j < SC2; j++) {
                p = DSYN * p + b1[j];
                float v = p + r;
                float s = (v >= THETA) ? 1.0f : 0.0f;
                r = DREF * (r - 2.0f * THETA * s);
                oo[(size_t)j * OO] = s;
            }
        }
    }
}

// ---------------------------------------------------------------------------
extern "C" void kernel_launch(void* const* d_in, const int* in_sizes, int n_in,
                              void* d_out, int out_size)
{
    const float* x  = (const float*)d_in[0];   // (64, 500, 1250)
    const float* W1 = (const float*)d_in[1];   // (512, 1250)
    const float* W2 = (const float*)d_in[2];   // (2, 512)
    float* out = (float*)d_out;                // (64, 500, 2)

    __half*        w1h; cudaGetSymbolAddress((void**)&w1h, g_w1h);
    __half*        u1;  cudaGetSymbolAddress((void**)&u1,  g_u1);
    __nv_bfloat16* s1;  cudaGetSymbolAddress((void**)&s1,  g_s1);
    float*         u2;  cudaGetSymbolAddress((void**)&u2,  g_u2);

    {
        long n = (long)HH * KP;
        cvt_w1_kernel<<<(unsigned)((n + 255) / 256), 256>>>(W1, w1h);
    }

    cudaFuncSetAttribute(gemm1_mma_kernel,
                         cudaFuncAttributeMaxDynamicSharedMemorySize, SMEM_GEMM);
    dim3 g1(HH / BN, MM / BM);                // (2, 500)
    gemm1_mma_kernel<<<g1, 256, SMEM_GEMM>>>(x, w1h, u1);

    dim3 g2(BV, HH / 128);                    // (64, 4)
    scan1_kernel<<<g2, 128>>>(u1, s1);

    gemm2_kernel<<<(MM * 32 + 255) / 256, 256>>>(s1, W2, u2);

    scan2_kernel<<<1, 128>>>(u2, out);
}

// round 13
// speedup vs baseline: 1.4205x; 1.0206x over previous
#include <cuda_runtime.h>
#include <cuda_bf16.h>
#include <cuda_fp16.h>
#include <cstdint>

// Problem dims
#define BV   64
#define TT   500
#define FIN  1250
#define KP   1280          // FIN padded for B
#define HH   512
#define OO   2
#define MM   (BV * TT)     // 32000

// Neuron constants
#define DSYN  0.9048374180359595f
#define DREF  0.36787944117144233f
#define THETA 10.0f

// Scratch (device globals: allocation-free rule)
__device__ __align__(16) __half g_w1h[(size_t)HH * KP];  // 1.3 MB
__device__ __align__(16) __half g_u1 [(size_t)MM * HH];  // 32 MB (fp16)
__device__ __align__(16) float  g_u2 [(size_t)MM * OO];  // 256 KB

// ---------------------------------------------------------------------------
// PTX helpers
// ---------------------------------------------------------------------------
__device__ __forceinline__ void ldsm_x4(uint32_t &r0, uint32_t &r1,
                                        uint32_t &r2, uint32_t &r3,
                                        uint32_t addr)
{
    asm volatile("ldmatrix.sync.aligned.m8n8.x4.shared.b16 {%0,%1,%2,%3}, [%4];"
                 : "=r"(r0), "=r"(r1), "=r"(r2), "=r"(r3) : "r"(addr));
}

// fp16-accumulator MMA: D(2 regs) = A(4) * B(2) + D
__device__ __forceinline__ void mma16816_f16(uint32_t* c, const uint32_t* a,
                                             const uint32_t b0, const uint32_t b1)
{
    asm volatile(
        "mma.sync.aligned.m16n8k16.row.col.f16.f16.f16.f16 "
        "{%0,%1}, {%2,%3,%4,%5}, {%6,%7}, {%0,%1};"
        : "+r"(c[0]), "+r"(c[1])
        : "r"(a[0]), "r"(a[1]), "r"(a[2]), "r"(a[3]), "r"(b0), "r"(b1));
}

__device__ __forceinline__ void cp_async16(uint32_t smem_addr, const void* gptr)
{
    asm volatile("cp.async.cg.shared.global [%0], [%1], 16;"
                 :: "r"(smem_addr), "l"(gptr));
}
__device__ __forceinline__ void cp_commit()
{
    asm volatile("cp.async.commit_group;");
}
__device__ __forceinline__ void cp_wait0()
{
    asm volatile("cp.async.wait_group 0;");
}

// ---------------------------------------------------------------------------
// K0: W1 fp32 -> fp16, pad K 1250 -> 1280 (L2-resident thereafter)
// ---------------------------------------------------------------------------
__global__ __launch_bounds__(256) void cvt_w1_kernel(
    const float* __restrict__ W, __half* __restrict__ Wh)
{
    long i = (long)blockIdx.x * blockDim.x + threadIdx.x;
    if (i >= (long)HH * KP) return;
    int  k = (int)(i % KP);
    long h = i / KP;
    float v = (k < FIN) ? W[h * FIN + k] : 0.0f;
    Wh[i] = __float2half(v);
}

// ---------------------------------------------------------------------------
// K1: U1[m,h] = sum_k X[m,k] * W1[h,k]   (fp16 HMMA, fp16 accum, fp16 out)
// R10-proven: BM=64, BN=256, BK=64, occ 2. 8 warps as 2(m) x 4(n),
// warp tile 32x64. A: fp32 LDG -> regs -> fp16 STS, one chunk ahead.
// B: cp.async dbl buffer. Rows padded to 72 halves (144B).
// ---------------------------------------------------------------------------
#define BM 64
#define BN 256
#define BK 64
#define LDA 72
#define ROWB (LDA * 2)             // 144 bytes/row
#define ABUFB (BM * ROWB)          // 9216
#define BBUFB (BN * ROWB)          // 36864
#define SMEM_GEMM (2 * ABUFB + 2 * BBUFB)   // 92160
#define NKCH (KP / BK)             // 20

__global__ __launch_bounds__(256, 2) void gemm1_mma_kernel(
    const float* __restrict__ X,
    const __half* __restrict__ Wh,
    __half* __restrict__ U)
{
    extern __shared__ __align__(16) char smem[];
    char* As = smem;
    char* Bs = smem + 2 * ABUFB;

    const int tid  = threadIdx.x;
    const int warp = tid >> 5;
    const int lane = tid & 31;
    const int wm   = warp >> 2;            // 0..1 -> m off wm*32
    const int wn   = warp & 3;             // 0..3 -> n off wn*64
    const int bm   = blockIdx.y * BM;
    const int bn   = blockIdx.x * BN;

    uint32_t acc[2][8][2];                 // fp16x2 accumulators
#pragma unroll
    for (int i = 0; i < 2; i++)
#pragma unroll
        for (int j = 0; j < 8; j++) {
            acc[i][j][0] = 0u;
            acc[i][j][1] = 0u;
        }

    const uint32_t asB = (uint32_t)__cvta_generic_to_shared(As);
    const uint32_t bsB = (uint32_t)__cvta_generic_to_shared(Bs);

    // A: 64 rows x 32 float2 = 2048 units, 8/thread. row=(tid>>5)+j*8, c2=tid&31
    const int aRowL = tid >> 5;
    const int aC2   = tid & 31;
    // B: 256 rows x 128B = 2048 x16B, 8/thread. row=(tid>>3)+j*32, g=tid&7
    const int bRowL = tid >> 3;
    const int bG    = tid & 7;

    const float* Xb = X + (size_t)bm * FIN;

    float2 pre[8];

    // ---- preload chunk 0
    {
#pragma unroll
        for (int j = 0; j < 8; j++) {
            int row = aRowL + j * 8;
            pre[j] = *(const float2*)(Xb + (size_t)row * FIN + aC2 * 2);
        }
#pragma unroll
        for (int j = 0; j < 8; j++) {
            int row = aRowL + j * 8;
            __half2 h2 = __float22half2_rn(pre[j]);
            *(__half2*)(As + row * ROWB + aC2 * 4) = h2;
        }
#pragma unroll
        for (int j = 0; j < 8; j++) {
            int row = bRowL + j * 32;
            cp_async16(bsB + (uint32_t)(row * ROWB + bG * 16),
                       Wh + (size_t)(bn + row) * KP + bG * 8);
        }
        cp_commit();
    }

    const uint32_t aRowOff = (uint32_t)(wm * 32 + (lane & 15));
    const uint32_t aColOff = (uint32_t)((lane >> 4) * 16);
    const uint32_t bRowOff = (uint32_t)(wn * 64 + ((lane >> 4) & 1) * 8 + (lane & 7));
    const uint32_t bColOff = (uint32_t)(((lane >> 3) & 1) * 16);

    for (int kt = 0; kt < NKCH; kt++) {
        cp_wait0();
        __syncthreads();                   // buffer kt&1 ready; nb free

        const int nb = (kt + 1) & 1;
        const bool more = (kt + 1 < NKCH);

        if (more) {
            const int kn = (kt + 1) * BK;
            if (kt + 1 < NKCH - 1) {
#pragma unroll
                for (int j = 0; j < 8; j++) {
                    int row = aRowL + j * 8;
                    pre[j] = *(const float2*)(Xb + (size_t)row * FIN + kn + aC2 * 2);
                }
            } else {                        // last chunk: k 1216..1279
#pragma unroll
                for (int j = 0; j < 8; j++) {
                    int row = aRowL + j * 8;
                    int k   = kn + aC2 * 2;
                    pre[j] = (k < FIN)
                        ? *(const float2*)(Xb + (size_t)row * FIN + k)
                        : make_float2(0.0f, 0.0f);
                }
            }
#pragma unroll
            for (int j = 0; j < 8; j++) {
                int row = bRowL + j * 32;
                cp_async16(bsB + (uint32_t)(nb * BBUFB + row * ROWB + bG * 16),
                           Wh + (size_t)(bn + row) * KP + kn + bG * 8);
            }
            cp_commit();
        } else {
            cp_commit();
        }

        const uint32_t aBase = asB + (uint32_t)((kt & 1) * ABUFB);
        const uint32_t bBase = bsB + (uint32_t)((kt & 1) * BBUFB);

#pragma unroll
        for (int ks = 0; ks < 4; ks++) {
            uint32_t a[2][4];
#pragma unroll
            for (int mt = 0; mt < 2; mt++) {
                uint32_t addr = aBase + (aRowOff + mt * 16) * ROWB
                                      + ks * 32 + aColOff;
                ldsm_x4(a[mt][0], a[mt][1], a[mt][2], a[mt][3], addr);
            }
            uint32_t b[4][4];
#pragma unroll
            for (int p = 0; p < 4; p++) {
                uint32_t addr = bBase + (bRowOff + p * 16) * ROWB
                                      + ks * 32 + bColOff;
                ldsm_x4(b[p][0], b[p][1], b[p][2], b[p][3], addr);
            }
#pragma unroll
            for (int mt = 0; mt < 2; mt++)
#pragma unroll
                for (int nt = 0; nt < 8; nt++)
                    mma16816_f16(acc[mt][nt], a[mt],
                                 b[nt >> 1][(nt & 1) * 2],
                                 b[nt >> 1][(nt & 1) * 2 + 1]);
        }

        if (more) {
#pragma unroll
            for (int j = 0; j < 8; j++) {
                int row = aRowL + j * 8;
                __half2 h2 = __float22half2_rn(pre[j]);
                *(__half2*)(As + nb * ABUFB + row * ROWB + aC2 * 4) = h2;
            }
        }
    }

    // epilogue: raw fp16x2 stores (frag reg0 -> row, reg1 -> row+8)
    const int cr = lane >> 2;
    const int cc = (lane & 3) * 2;
#pragma unroll
    for (int mt = 0; mt < 2; mt++) {
#pragma unroll
        for (int nt = 0; nt < 8; nt++) {
            int row0 = bm + wm * 32 + mt * 16 + cr;
            int col  = bn + wn * 64 + nt * 8 + cc;
            *(uint32_t*)(U + (size_t)row0 * HH + col)       = acc[mt][nt][0];
            *(uint32_t*)(U + (size_t)(row0 + 8) * HH + col) = acc[mt][nt][1];
        }
    }
}

// ---------------------------------------------------------------------------
// K2: fused PSP + spike scan + layer-2 projection, layer 1.
// One thread per (b,h) chain. On the (rare) spike, accumulate W2 columns
// into U2[b,t,:] via atomics — this replaces the separate gemm2 pass and
// eliminates the s1 buffer entirely. U2 must be pre-zeroed.
// ---------------------------------------------------------------------------
#define SCH 10
__global__ __launch_bounds__(128) void scan1_kernel(
    const __half* __restrict__ U1, const float* __restrict__ W2,
    float* __restrict__ U2)
{
    const int b = blockIdx.x;
    const int h = blockIdx.y * 128 + threadIdx.x;
    const __half* up = U1 + (size_t)b * TT * HH + h;
    float*        u2 = U2 + (size_t)b * TT * OO;

    const float w20 = W2[h];
    const float w21 = W2[HH + h];

    float b0[SCH], b1[SCH];
#pragma unroll
    for (int j = 0; j < SCH; j++) b0[j] = __half2float(up[(size_t)j * HH]);

    float p = 0.0f, r = 0.0f;
    const int NC = TT / SCH;             // 50 (even)
    for (int c = 0; c < NC; c += 2) {
        {
            const __half* nx = up + (size_t)(c + 1) * SCH * HH;
#pragma unroll
            for (int j = 0; j < SCH; j++) b1[j] = __half2float(nx[(size_t)j * HH]);
        }
#pragma unroll
        for (int j = 0; j < SCH; j++) {
            p = DSYN * p + b0[j];
            float v = p + r;
            if (v >= THETA) {
                r = DREF * (r - 2.0f * THETA);
                int t = c * SCH + j;
                atomicAdd(&u2[t * OO + 0], w20);
                atomicAdd(&u2[t * OO + 1], w21);
            } else {
                r = DREF * r;
            }
        }
        if (c + 2 < NC) {
            const __half* nx = up + (size_t)(c + 2) * SCH * HH;
#pragma unroll
            for (int j = 0; j < SCH; j++) b0[j] = __half2float(nx[(size_t)j * HH]);
        }
#pragma unroll
        for (int j = 0; j < SCH; j++) {
            p = DSYN * p + b1[j];
            float v = p + r;
            if (v >= THETA) {
                r = DREF * (r - 2.0f * THETA);
                int t = (c + 1) * SCH + j;
                atomicAdd(&u2[t * OO + 0], w20);
                atomicAdd(&u2[t * OO + 1], w21);
            } else {
                r = DREF * r;
            }
        }
    }
}

// ---------------------------------------------------------------------------
// K4: scan layer 2. Explicit two-named-buffer pipeline.
// ---------------------------------------------------------------------------
#define SC2 20
__global__ __launch_bounds__(128) void scan2_kernel(
    const float* __restrict__ U2, float* __restrict__ out)
{
    const int i = threadIdx.x;
    const int b = i >> 1;
    const int o = i & 1;
    const float* up = U2  + (size_t)b * TT * OO + o;
    float*       op = out + (size_t)b * TT * OO + o;

    float b0[SC2], b1[SC2];
#pragma unroll
    for (int j = 0; j < SC2; j++) b0[j] = up[(size_t)j * OO];

    float p = 0.0f, r = 0.0f;
    const int NC = TT / SC2;             // 25 (odd)
    for (int c = 0; c < NC; c += 2) {
        if (c + 1 < NC) {
            const float* nx = up + (size_t)(c + 1) * SC2 * OO;
#pragma unroll
            for (int j = 0; j < SC2; j++) b1[j] = nx[(size_t)j * OO];
        }
        {
            float* oo = op + (size_t)c * SC2 * OO;
#pragma unroll
            for (int j = 0; j < SC2; j++) {
                p = DSYN * p + b0[j];
                float v = p + r;
                float s = (v >= THETA) ? 1.0f : 0.0f;
                r = DREF * (r - 2.0f * THETA * s);
                oo[(size_t)j * OO] = s;
            }
        }
        if (c + 2 < NC) {
            const float* nx = up + (size_t)(c + 2) * SC2 * OO;
#pragma unroll
            for (int j = 0; j < SC2; j++) b0[j] = nx[(size_t)j * OO];
        }
        if (c + 1 < NC) {
            float* oo = op + (size_t)(c + 1) * SC2 * OO;
#pragma unroll
            for (int j = 0; j < SC2; j++) {
                p = DSYN * p + b1[j];
                float v = p + r;
                float s = (v >= THETA) ? 1.0f : 0.0f;
                r = DREF * (r - 2.0f * THETA * s);
                oo[(size_t)j * OO] = s;
            }
        }
    }
}

// ---------------------------------------------------------------------------
extern "C" void kernel_launch(void* const* d_in, const int* in_sizes, int n_in,
                              void* d_out, int out_size)
{
    const float* x  = (const float*)d_in[0];   // (64, 500, 1250)
    const float* W1 = (const float*)d_in[1];   // (512, 1250)
    const float* W2 = (const float*)d_in[2];   // (2, 512)
    float* out = (float*)d_out;                // (64, 500, 2)

    __half* w1h; cudaGetSymbolAddress((void**)&w1h, g_w1h);
    __half* u1;  cudaGetSymbolAddress((void**)&u1,  g_u1);
    float*  u2;  cudaGetSymbolAddress((void**)&u2,  g_u2);

    // zero the layer-2 membrane accumulator (graph-capturable memset node)
    cudaMemsetAsync(u2, 0, (size_t)MM * OO * sizeof(float));

    {
        long n = (long)HH * KP;
        cvt_w1_kernel<<<(unsigned)((n + 255) / 256), 256>>>(W1, w1h);
    }

    cudaFuncSetAttribute(gemm1_mma_kernel,
                         cudaFuncAttributeMaxDynamicSharedMemorySize, SMEM_GEMM);
    dim3 g1(HH / BN, MM / BM);                // (2, 500)
    gemm1_mma_kernel<<<g1, 256, SMEM_GEMM>>>(x, w1h, u1);

    dim3 g2(BV, HH / 128);                    // (64, 4)
    scan1_kernel<<<g2, 128>>>(u1, W2, u2);

    scan2_kernel<<<1, 128>>>(u2, out);
}

// round 14
// speedup vs baseline: 1.5556x; 1.0950x over previous
#include <cuda_runtime.h>
#include <cuda_bf16.h>
#include <cuda_fp16.h>
#include <cstdint>

// Problem dims
#define BV   64
#define TT   500
#define FIN  1250
#define KP   1280          // FIN padded for B
#define HH   512
#define OO   2
#define MM   (BV * TT)     // 32000

// Neuron constants
#define DSYN  0.9048374180359595f
#define DREF  0.36787944117144233f
#define THETA 10.0f

// Scratch (device globals: allocation-free rule)
__device__ __align__(16) __half g_w1h[(size_t)HH * KP];  // 1.3 MB
__device__ __align__(16) __half g_u1 [(size_t)MM * HH];  // 32 MB (fp16)
__device__ __align__(16) float  g_u2 [(size_t)MM * OO];  // 256 KB

// ---------------------------------------------------------------------------
// PTX helpers
// ---------------------------------------------------------------------------
__device__ __forceinline__ void ldsm_x4(uint32_t &r0, uint32_t &r1,
                                        uint32_t &r2, uint32_t &r3,
                                        uint32_t addr)
{
    asm volatile("ldmatrix.sync.aligned.m8n8.x4.shared.b16 {%0,%1,%2,%3}, [%4];"
                 : "=r"(r0), "=r"(r1), "=r"(r2), "=r"(r3) : "r"(addr));
}

// fp16-accumulator MMA: D(2 regs) = A(4) * B(2) + D
__device__ __forceinline__ void mma16816_f16(uint32_t* c, const uint32_t* a,
                                             const uint32_t b0, const uint32_t b1)
{
    asm volatile(
        "mma.sync.aligned.m16n8k16.row.col.f16.f16.f16.f16 "
        "{%0,%1}, {%2,%3,%4,%5}, {%6,%7}, {%0,%1};"
        : "+r"(c[0]), "+r"(c[1])
        : "r"(a[0]), "r"(a[1]), "r"(a[2]), "r"(a[3]), "r"(b0), "r"(b1));
}

__device__ __forceinline__ void cp_async16(uint32_t smem_addr, const void* gptr)
{
    asm volatile("cp.async.cg.shared.global [%0], [%1], 16;"
                 :: "r"(smem_addr), "l"(gptr));
}
__device__ __forceinline__ void cp_commit()
{
    asm volatile("cp.async.commit_group;");
}
__device__ __forceinline__ void cp_wait0()
{
    asm volatile("cp.async.wait_group 0;");
}

// ---------------------------------------------------------------------------
// K0: W1 fp32 -> fp16, pad K 1250 -> 1280 (L2-resident thereafter)
// ---------------------------------------------------------------------------
__global__ __launch_bounds__(256) void cvt_w1_kernel(
    const float* __restrict__ W, __half* __restrict__ Wh)
{
    long i = (long)blockIdx.x * blockDim.x + threadIdx.x;
    if (i >= (long)HH * KP) return;
    int  k = (int)(i % KP);
    long h = i / KP;
    float v = (k < FIN) ? W[h * FIN + k] : 0.0f;
    Wh[i] = __float2half(v);
}

// ---------------------------------------------------------------------------
// K1: U1[m,h] = sum_k X[m,k] * W1[h,k]   (fp16 HMMA, fp16 accum, fp16 out)
// R10-proven: BM=64, BN=256, BK=64, occ 2. 8 warps as 2(m) x 4(n),
// warp tile 32x64. A: fp32 LDG -> regs -> fp16 STS, one chunk ahead.
// B: cp.async dbl buffer. Rows padded to 72 halves (144B).
// ---------------------------------------------------------------------------
#define BM 64
#define BN 256
#define BK 64
#define LDA 72
#define ROWB (LDA * 2)             // 144 bytes/row
#define ABUFB (BM * ROWB)          // 9216
#define BBUFB (BN * ROWB)          // 36864
#define SMEM_GEMM (2 * ABUFB + 2 * BBUFB)   // 92160
#define NKCH (KP / BK)             // 20

__global__ __launch_bounds__(256, 2) void gemm1_mma_kernel(
    const float* __restrict__ X,
    const __half* __restrict__ Wh,
    __half* __restrict__ U)
{
    extern __shared__ __align__(16) char smem[];
    char* As = smem;
    char* Bs = smem + 2 * ABUFB;

    const int tid  = threadIdx.x;
    const int warp = tid >> 5;
    const int lane = tid & 31;
    const int wm   = warp >> 2;            // 0..1 -> m off wm*32
    const int wn   = warp & 3;             // 0..3 -> n off wn*64
    const int bm   = blockIdx.y * BM;
    const int bn   = blockIdx.x * BN;

    uint32_t acc[2][8][2];                 // fp16x2 accumulators
#pragma unroll
    for (int i = 0; i < 2; i++)
#pragma unroll
        for (int j = 0; j < 8; j++) {
            acc[i][j][0] = 0u;
            acc[i][j][1] = 0u;
        }

    const uint32_t asB = (uint32_t)__cvta_generic_to_shared(As);
    const uint32_t bsB = (uint32_t)__cvta_generic_to_shared(Bs);

    // A: 64 rows x 32 float2 = 2048 units, 8/thread. row=(tid>>5)+j*8, c2=tid&31
    const int aRowL = tid >> 5;
    const int aC2   = tid & 31;
    // B: 256 rows x 128B = 2048 x16B, 8/thread. row=(tid>>3)+j*32, g=tid&7
    const int bRowL = tid >> 3;
    const int bG    = tid & 7;

    const float* Xb = X + (size_t)bm * FIN;

    float2 pre[8];

    // ---- preload chunk 0
    {
#pragma unroll
        for (int j = 0; j < 8; j++) {
            int row = aRowL + j * 8;
            pre[j] = *(const float2*)(Xb + (size_t)row * FIN + aC2 * 2);
        }
#pragma unroll
        for (int j = 0; j < 8; j++) {
            int row = aRowL + j * 8;
            __half2 h2 = __float22half2_rn(pre[j]);
            *(__half2*)(As + row * ROWB + aC2 * 4) = h2;
        }
#pragma unroll
        for (int j = 0; j < 8; j++) {
            int row = bRowL + j * 32;
            cp_async16(bsB + (uint32_t)(row * ROWB + bG * 16),
                       Wh + (size_t)(bn + row) * KP + bG * 8);
        }
        cp_commit();
    }

    const uint32_t aRowOff = (uint32_t)(wm * 32 + (lane & 15));
    const uint32_t aColOff = (uint32_t)((lane >> 4) * 16);
    const uint32_t bRowOff = (uint32_t)(wn * 64 + ((lane >> 4) & 1) * 8 + (lane & 7));
    const uint32_t bColOff = (uint32_t)(((lane >> 3) & 1) * 16);

    for (int kt = 0; kt < NKCH; kt++) {
        cp_wait0();
        __syncthreads();                   // buffer kt&1 ready; nb free

        const int nb = (kt + 1) & 1;
        const bool more = (kt + 1 < NKCH);

        if (more) {
            const int kn = (kt + 1) * BK;
            if (kt + 1 < NKCH - 1) {
#pragma unroll
                for (int j = 0; j < 8; j++) {
                    int row = aRowL + j * 8;
                    pre[j] = *(const float2*)(Xb + (size_t)row * FIN + kn + aC2 * 2);
                }
            } else {                        // last chunk: k 1216..1279
#pragma unroll
                for (int j = 0; j < 8; j++) {
                    int row = aRowL + j * 8;
                    int k   = kn + aC2 * 2;
                    pre[j] = (k < FIN)
                        ? *(const float2*)(Xb + (size_t)row * FIN + k)
                        : make_float2(0.0f, 0.0f);
                }
            }
#pragma unroll
            for (int j = 0; j < 8; j++) {
                int row = bRowL + j * 32;
                cp_async16(bsB + (uint32_t)(nb * BBUFB + row * ROWB + bG * 16),
                           Wh + (size_t)(bn + row) * KP + kn + bG * 8);
            }
            cp_commit();
        } else {
            cp_commit();
        }

        const uint32_t aBase = asB + (uint32_t)((kt & 1) * ABUFB);
        const uint32_t bBase = bsB + (uint32_t)((kt & 1) * BBUFB);

#pragma unroll
        for (int ks = 0; ks < 4; ks++) {
            uint32_t a[2][4];
#pragma unroll
            for (int mt = 0; mt < 2; mt++) {
                uint32_t addr = aBase + (aRowOff + mt * 16) * ROWB
                                      + ks * 32 + aColOff;
                ldsm_x4(a[mt][0], a[mt][1], a[mt][2], a[mt][3], addr);
            }
            uint32_t b[4][4];
#pragma unroll
            for (int p = 0; p < 4; p++) {
                uint32_t addr = bBase + (bRowOff + p * 16) * ROWB
                                      + ks * 32 + bColOff;
                ldsm_x4(b[p][0], b[p][1], b[p][2], b[p][3], addr);
            }
#pragma unroll
            for (int mt = 0; mt < 2; mt++)
#pragma unroll
                for (int nt = 0; nt < 8; nt++)
                    mma16816_f16(acc[mt][nt], a[mt],
                                 b[nt >> 1][(nt & 1) * 2],
                                 b[nt >> 1][(nt & 1) * 2 + 1]);
        }

        if (more) {
#pragma unroll
            for (int j = 0; j < 8; j++) {
                int row = aRowL + j * 8;
                __half2 h2 = __float22half2_rn(pre[j]);
                *(__half2*)(As + nb * ABUFB + row * ROWB + aC2 * 4) = h2;
            }
        }
    }

    // epilogue: raw fp16x2 stores (frag reg0 -> row, reg1 -> row+8)
    const int cr = lane >> 2;
    const int cc = (lane & 3) * 2;
#pragma unroll
    for (int mt = 0; mt < 2; mt++) {
#pragma unroll
        for (int nt = 0; nt < 8; nt++) {
            int row0 = bm + wm * 32 + mt * 16 + cr;
            int col  = bn + wn * 64 + nt * 8 + cc;
            *(uint32_t*)(U + (size_t)row0 * HH + col)       = acc[mt][nt][0];
            *(uint32_t*)(U + (size_t)(row0 + 8) * HH + col) = acc[mt][nt][1];
        }
    }
}

// ---------------------------------------------------------------------------
// K2: fused PSP + spike scan + layer-2 projection, layer 1 (R13-proven).
// One thread per (b,h) chain; rare spikes accumulate W2 into U2 via atomics.
// ---------------------------------------------------------------------------
#define SCH 10
__global__ __launch_bounds__(128) void scan1_kernel(
    const __half* __restrict__ U1, const float* __restrict__ W2,
    float* __restrict__ U2)
{
    const int b = blockIdx.x;
    const int h = blockIdx.y * 128 + threadIdx.x;
    const __half* up = U1 + (size_t)b * TT * HH + h;
    float*        u2 = U2 + (size_t)b * TT * OO;

    const float w20 = W2[h];
    const float w21 = W2[HH + h];

    float b0[SCH], b1[SCH];
#pragma unroll
    for (int j = 0; j < SCH; j++) b0[j] = __half2float(up[(size_t)j * HH]);

    float p = 0.0f, r = 0.0f;
    const int NC = TT / SCH;             // 50 (even)
    for (int c = 0; c < NC; c += 2) {
        {
            const __half* nx = up + (size_t)(c + 1) * SCH * HH;
#pragma unroll
            for (int j = 0; j < SCH; j++) b1[j] = __half2float(nx[(size_t)j * HH]);
        }
#pragma unroll
        for (int j = 0; j < SCH; j++) {
            p = DSYN * p + b0[j];
            float v = p + r;
            if (v >= THETA) {
                r = DREF * (r - 2.0f * THETA);
                int t = c * SCH + j;
                atomicAdd(&u2[t * OO + 0], w20);
                atomicAdd(&u2[t * OO + 1], w21);
            } else {
                r = DREF * r;
            }
        }
        if (c + 2 < NC) {
            const __half* nx = up + (size_t)(c + 2) * SCH * HH;
#pragma unroll
            for (int j = 0; j < SCH; j++) b0[j] = __half2float(nx[(size_t)j * HH]);
        }
#pragma unroll
        for (int j = 0; j < SCH; j++) {
            p = DSYN * p + b1[j];
            float v = p + r;
            if (v >= THETA) {
                r = DREF * (r - 2.0f * THETA);
                int t = (c + 1) * SCH + j;
                atomicAdd(&u2[t * OO + 0], w20);
                atomicAdd(&u2[t * OO + 1], w21);
            } else {
                r = DREF * r;
            }
        }
    }
}

// ---------------------------------------------------------------------------
// K4: scan layer 2 — smem-staged. One block per batch element b:
// 256 threads stage u2[b,:,:] (1000 floats, coalesced float4), then
// threads 0-1 run the two (b,o) recurrences out of shared memory.
// ---------------------------------------------------------------------------
__global__ __launch_bounds__(256) void scan2_kernel(
    const float* __restrict__ U2, float* __restrict__ out)
{
    __shared__ float us[TT * OO];          // 4000 B
    const int b = blockIdx.x;
    const float* up = U2 + (size_t)b * TT * OO;

    // stage: 1000 floats = 250 float4
    for (int i = threadIdx.x; i < (TT * OO) / 4; i += blockDim.x) {
        ((float4*)us)[i] = ((const float4*)up)[i];
    }
    __syncthreads();

    if (threadIdx.x < OO) {
        const int o = threadIdx.x;
        float*    op = out + (size_t)b * TT * OO + o;

        float p = 0.0f, r = 0.0f;
#pragma unroll 10
        for (int t = 0; t < TT; t++) {
            p = DSYN * p + us[t * OO + o];
            float v = p + r;
            float s = (v >= THETA) ? 1.0f : 0.0f;
            r = DREF * (r - 2.0f * THETA * s);
            op[(size_t)t * OO] = s;
        }
    }
}

// ---------------------------------------------------------------------------
extern "C" void kernel_launch(void* const* d_in, const int* in_sizes, int n_in,
                              void* d_out, int out_size)
{
    const float* x  = (const float*)d_in[0];   // (64, 500, 1250)
    const float* W1 = (const float*)d_in[1];   // (512, 1250)
    const float* W2 = (const float*)d_in[2];   // (2, 512)
    float* out = (float*)d_out;                // (64, 500, 2)

    __half* w1h; cudaGetSymbolAddress((void**)&w1h, g_w1h);
    __half* u1;  cudaGetSymbolAddress((void**)&u1,  g_u1);
    float*  u2;  cudaGetSymbolAddress((void**)&u2,  g_u2);

    // zero the layer-2 membrane accumulator (graph-capturable memset node)
    cudaMemsetAsync(u2, 0, (size_t)MM * OO * sizeof(float));

    {
        long n = (long)HH * KP;
        cvt_w1_kernel<<<(unsigned)((n + 255) / 256), 256>>>(W1, w1h);
    }

    cudaFuncSetAttribute(gemm1_mma_kernel,
                         cudaFuncAttributeMaxDynamicSharedMemorySize, SMEM_GEMM);
    dim3 g1(HH / BN, MM / BM);                // (2, 500)
    gemm1_mma_kernel<<<g1, 256, SMEM_GEMM>>>(x, w1h, u1);

    dim3 g2(BV, HH / 128);                    // (64, 4)
    scan1_kernel<<<g2, 128>>>(u1, W2, u2);

    scan2_kernel<<<BV, 256>>>(u2, out);
}

// round 15
// speedup vs baseline: 1.6252x; 1.0448x over previous
#include <cuda_runtime.h>
#include <cuda_bf16.h>
#include <cuda_fp16.h>
#include <cstdint>

// Problem dims
#define BV   64
#define TT   500
#define FIN  1250
#define KP   1280          // FIN padded for B
#define HH   512
#define OO   2
#define MM   (BV * TT)     // 32000

// Neuron constants
#define DSYN  0.9048374180359595f
#define DREF  0.36787944117144233f
#define THETA 10.0f

// Scratch (device globals: allocation-free rule)
__device__ __align__(16) __half g_w1h[(size_t)HH * KP];  // 1.3 MB
__device__ __align__(16) __half g_u1 [(size_t)MM * HH];  // 32 MB (fp16)
__device__ __align__(16) float  g_u2 [(size_t)MM * OO];  // 256 KB

// ---------------------------------------------------------------------------
// PTX helpers
// ---------------------------------------------------------------------------
__device__ __forceinline__ void ldsm_x4(uint32_t &r0, uint32_t &r1,
                                        uint32_t &r2, uint32_t &r3,
                                        uint32_t addr)
{
    asm volatile("ldmatrix.sync.aligned.m8n8.x4.shared.b16 {%0,%1,%2,%3}, [%4];"
                 : "=r"(r0), "=r"(r1), "=r"(r2), "=r"(r3) : "r"(addr));
}

// fp16-accumulator MMA: D(2 regs) = A(4) * B(2) + D
__device__ __forceinline__ void mma16816_f16(uint32_t* c, const uint32_t* a,
                                             const uint32_t b0, const uint32_t b1)
{
    asm volatile(
        "mma.sync.aligned.m16n8k16.row.col.f16.f16.f16.f16 "
        "{%0,%1}, {%2,%3,%4,%5}, {%6,%7}, {%0,%1};"
        : "+r"(c[0]), "+r"(c[1])
        : "r"(a[0]), "r"(a[1]), "r"(a[2]), "r"(a[3]), "r"(b0), "r"(b1));
}

__device__ __forceinline__ void cp_async16(uint32_t smem_addr, const void* gptr)
{
    asm volatile("cp.async.cg.shared.global [%0], [%1], 16;"
                 :: "r"(smem_addr), "l"(gptr));
}
__device__ __forceinline__ void cp_commit()
{
    asm volatile("cp.async.commit_group;");
}
__device__ __forceinline__ void cp_wait0()
{
    asm volatile("cp.async.wait_group 0;");
}

// ---------------------------------------------------------------------------
// K0: W1 fp32 -> fp16, pad K 1250 -> 1280 (L2-resident thereafter)
// ---------------------------------------------------------------------------
__global__ __launch_bounds__(256) void cvt_w1_kernel(
    const float* __restrict__ W, __half* __restrict__ Wh)
{
    long i = (long)blockIdx.x * blockDim.x + threadIdx.x;
    if (i >= (long)HH * KP) return;
    int  k = (int)(i % KP);
    long h = i / KP;
    float v = (k < FIN) ? W[h * FIN + k] : 0.0f;
    Wh[i] = __float2half(v);
}

// ---------------------------------------------------------------------------
// K1: U1[m,h] = sum_k X[m,k] * W1[h,k]   (fp16 HMMA, fp16 accum, fp16 out)
// R10-proven: BM=64, BN=256, BK=64, occ 2. 8 warps as 2(m) x 4(n),
// warp tile 32x64. A: fp32 LDG -> regs -> fp16 STS, one chunk ahead.
// B: cp.async dbl buffer. Rows padded to 72 halves (144B).
// ---------------------------------------------------------------------------
#define BM 64
#define BN 256
#define BK 64
#define LDA 72
#define ROWB (LDA * 2)             // 144 bytes/row
#define ABUFB (BM * ROWB)          // 9216
#define BBUFB (BN * ROWB)          // 36864
#define SMEM_GEMM (2 * ABUFB + 2 * BBUFB)   // 92160
#define NKCH (KP / BK)             // 20

__global__ __launch_bounds__(256, 2) void gemm1_mma_kernel(
    const float* __restrict__ X,
    const __half* __restrict__ Wh,
    __half* __restrict__ U)
{
    extern __shared__ __align__(16) char smem[];
    char* As = smem;
    char* Bs = smem + 2 * ABUFB;

    const int tid  = threadIdx.x;
    const int warp = tid >> 5;
    const int lane = tid & 31;
    const int wm   = warp >> 2;            // 0..1 -> m off wm*32
    const int wn   = warp & 3;             // 0..3 -> n off wn*64
    const int bm   = blockIdx.y * BM;
    const int bn   = blockIdx.x * BN;

    uint32_t acc[2][8][2];                 // fp16x2 accumulators
#pragma unroll
    for (int i = 0; i < 2; i++)
#pragma unroll
        for (int j = 0; j < 8; j++) {
            acc[i][j][0] = 0u;
            acc[i][j][1] = 0u;
        }

    const uint32_t asB = (uint32_t)__cvta_generic_to_shared(As);
    const uint32_t bsB = (uint32_t)__cvta_generic_to_shared(Bs);

    // A: 64 rows x 32 float2 = 2048 units, 8/thread. row=(tid>>5)+j*8, c2=tid&31
    const int aRowL = tid >> 5;
    const int aC2   = tid & 31;
    // B: 256 rows x 128B = 2048 x16B, 8/thread. row=(tid>>3)+j*32, g=tid&7
    const int bRowL = tid >> 3;
    const int bG    = tid & 7;

    const float* Xb = X + (size_t)bm * FIN;

    float2 pre[8];

    // ---- preload chunk 0
    {
#pragma unroll
        for (int j = 0; j < 8; j++) {
            int row = aRowL + j * 8;
            pre[j] = *(const float2*)(Xb + (size_t)row * FIN + aC2 * 2);
        }
#pragma unroll
        for (int j = 0; j < 8; j++) {
            int row = aRowL + j * 8;
            __half2 h2 = __float22half2_rn(pre[j]);
            *(__half2*)(As + row * ROWB + aC2 * 4) = h2;
        }
#pragma unroll
        for (int j = 0; j < 8; j++) {
            int row = bRowL + j * 32;
            cp_async16(bsB + (uint32_t)(row * ROWB + bG * 16),
                       Wh + (size_t)(bn + row) * KP + bG * 8);
        }
        cp_commit();
    }

    const uint32_t aRowOff = (uint32_t)(wm * 32 + (lane & 15));
    const uint32_t aColOff = (uint32_t)((lane >> 4) * 16);
    const uint32_t bRowOff = (uint32_t)(wn * 64 + ((lane >> 4) & 1) * 8 + (lane & 7));
    const uint32_t bColOff = (uint32_t)(((lane >> 3) & 1) * 16);

    for (int kt = 0; kt < NKCH; kt++) {
        cp_wait0();
        __syncthreads();                   // buffer kt&1 ready; nb free

        const int nb = (kt + 1) & 1;
        const bool more = (kt + 1 < NKCH);

        if (more) {
            const int kn = (kt + 1) * BK;
            if (kt + 1 < NKCH - 1) {
#pragma unroll
                for (int j = 0; j < 8; j++) {
                    int row = aRowL + j * 8;
                    pre[j] = *(const float2*)(Xb + (size_t)row * FIN + kn + aC2 * 2);
                }
            } else {                        // last chunk: k 1216..1279
#pragma unroll
                for (int j = 0; j < 8; j++) {
                    int row = aRowL + j * 8;
                    int k   = kn + aC2 * 2;
                    pre[j] = (k < FIN)
                        ? *(const float2*)(Xb + (size_t)row * FIN + k)
                        : make_float2(0.0f, 0.0f);
                }
            }
#pragma unroll
            for (int j = 0; j < 8; j++) {
                int row = bRowL + j * 32;
                cp_async16(bsB + (uint32_t)(nb * BBUFB + row * ROWB + bG * 16),
                           Wh + (size_t)(bn + row) * KP + kn + bG * 8);
            }
            cp_commit();
        } else {
            cp_commit();
        }

        const uint32_t aBase = asB + (uint32_t)((kt & 1) * ABUFB);
        const uint32_t bBase = bsB + (uint32_t)((kt & 1) * BBUFB);

#pragma unroll
        for (int ks = 0; ks < 4; ks++) {
            uint32_t a[2][4];
#pragma unroll
            for (int mt = 0; mt < 2; mt++) {
                uint32_t addr = aBase + (aRowOff + mt * 16) * ROWB
                                      + ks * 32 + aColOff;
                ldsm_x4(a[mt][0], a[mt][1], a[mt][2], a[mt][3], addr);
            }
            uint32_t b[4][4];
#pragma unroll
            for (int p = 0; p < 4; p++) {
                uint32_t addr = bBase + (bRowOff + p * 16) * ROWB
                                      + ks * 32 + bColOff;
                ldsm_x4(b[p][0], b[p][1], b[p][2], b[p][3], addr);
            }
#pragma unroll
            for (int mt = 0; mt < 2; mt++)
#pragma unroll
                for (int nt = 0; nt < 8; nt++)
                    mma16816_f16(acc[mt][nt], a[mt],
                                 b[nt >> 1][(nt & 1) * 2],
                                 b[nt >> 1][(nt & 1) * 2 + 1]);
        }

        if (more) {
#pragma unroll
            for (int j = 0; j < 8; j++) {
                int row = aRowL + j * 8;
                __half2 h2 = __float22half2_rn(pre[j]);
                *(__half2*)(As + nb * ABUFB + row * ROWB + aC2 * 4) = h2;
            }
        }
    }

    // epilogue: raw fp16x2 stores (frag reg0 -> row, reg1 -> row+8)
    const int cr = lane >> 2;
    const int cc = (lane & 3) * 2;
#pragma unroll
    for (int mt = 0; mt < 2; mt++) {
#pragma unroll
        for (int nt = 0; nt < 8; nt++) {
            int row0 = bm + wm * 32 + mt * 16 + cr;
            int col  = bn + wn * 64 + nt * 8 + cc;
            *(uint32_t*)(U + (size_t)row0 * HH + col)       = acc[mt][nt][0];
            *(uint32_t*)(U + (size_t)(row0 + 8) * HH + col) = acc[mt][nt][1];
        }
    }
}

// ---------------------------------------------------------------------------
// K2: fused PSP + spike scan + layer-2 projection, layer 1.
// One thread per (b,h) chain; rare spikes accumulate W2 into U2 via atomics.
// Prefetch depth 20 (MLP 20) with two named buffers, static indices only.
// NC = 25 (odd) -> second phase guarded.
// ---------------------------------------------------------------------------
#define SCH 20
__global__ __launch_bounds__(128) void scan1_kernel(
    const __half* __restrict__ U1, const float* __restrict__ W2,
    float* __restrict__ U2)
{
    const int b = blockIdx.x;
    const int h = blockIdx.y * 128 + threadIdx.x;
    const __half* up = U1 + (size_t)b * TT * HH + h;
    float*        u2 = U2 + (size_t)b * TT * OO;

    const float w20 = W2[h];
    const float w21 = W2[HH + h];

    float b0[SCH], b1[SCH];
#pragma unroll
    for (int j = 0; j < SCH; j++) b0[j] = __half2float(up[(size_t)j * HH]);

    float p = 0.0f, r = 0.0f;
    const int NC = TT / SCH;             // 25 (odd)
    for (int c = 0; c < NC; c += 2) {
        if (c + 1 < NC) {
            const __half* nx = up + (size_t)(c + 1) * SCH * HH;
#pragma unroll
            for (int j = 0; j < SCH; j++) b1[j] = __half2float(nx[(size_t)j * HH]);
        }
#pragma unroll
        for (int j = 0; j < SCH; j++) {
            p = DSYN * p + b0[j];
            float v = p + r;
            if (v >= THETA) {
                r = DREF * (r - 2.0f * THETA);
                int t = c * SCH + j;
                atomicAdd(&u2[t * OO + 0], w20);
                atomicAdd(&u2[t * OO + 1], w21);
            } else {
                r = DREF * r;
            }
        }
        if (c + 2 < NC) {
            const __half* nx = up + (size_t)(c + 2) * SCH * HH;
#pragma unroll
            for (int j = 0; j < SCH; j++) b0[j] = __half2float(nx[(size_t)j * HH]);
        }
        if (c + 1 < NC) {
#pragma unroll
            for (int j = 0; j < SCH; j++) {
                p = DSYN * p + b1[j];
                float v = p + r;
                if (v >= THETA) {
                    r = DREF * (r - 2.0f * THETA);
                    int t = (c + 1) * SCH + j;
                    atomicAdd(&u2[t * OO + 0], w20);
                    atomicAdd(&u2[t * OO + 1], w21);
                } else {
                    r = DREF * r;
                }
            }
        }
    }
}

// ---------------------------------------------------------------------------
// K4: scan layer 2 — smem-staged + chunked register prefetch in the chain.
// One block per batch element b: 256 threads stage u2[b,:,:] (coalesced
// float4), then threads 0-1 run the (b,o) recurrences with 20-deep
// register double-buffering out of shared memory (hides LDS latency).
// ---------------------------------------------------------------------------
#define SC2 20
__global__ __launch_bounds__(256) void scan2_kernel(
    const float* __restrict__ U2, float* __restrict__ out)
{
    __shared__ float us[TT * OO];          // 4000 B
    const int b = blockIdx.x;
    const float* up = U2 + (size_t)b * TT * OO;

    // stage: 1000 floats = 250 float4
    for (int i = threadIdx.x; i < (TT * OO) / 4; i += blockDim.x) {
        ((float4*)us)[i] = ((const float4*)up)[i];
    }
    __syncthreads();

    if (threadIdx.x < OO) {
        const int o = threadIdx.x;
        float*    op = out + (size_t)b * TT * OO + o;
        const float* usp = us + o;

        float b0[SC2], b1[SC2];
#pragma unroll
        for (int j = 0; j < SC2; j++) b0[j] = usp[j * OO];

        float p = 0.0f, r = 0.0f;
        const int NC = TT / SC2;           // 25 (odd)
        for (int c = 0; c < NC; c += 2) {
            if (c + 1 < NC) {
                const float* nx = usp + (c + 1) * SC2 * OO;
#pragma unroll
                for (int j = 0; j < SC2; j++) b1[j] = nx[j * OO];
            }
            {
                float* oo = op + (size_t)c * SC2 * OO;
#pragma unroll
                for (int j = 0; j < SC2; j++) {
                    p = DSYN * p + b0[j];
                    float v = p + r;
                    float s = (v >= THETA) ? 1.0f : 0.0f;
                    r = DREF * (r - 2.0f * THETA * s);
                    oo[(size_t)j * OO] = s;
                }
            }
            if (c + 2 < NC) {
                const float* nx = usp + (c + 2) * SC2 * OO;
#pragma unroll
                for (int j = 0; j < SC2; j++) b0[j] = nx[j * OO];
            }
            if (c + 1 < NC) {
                float* oo = op + (size_t)(c + 1) * SC2 * OO;
#pragma unroll
                for (int j = 0; j < SC2; j++) {
                    p = DSYN * p + b1[j];
                    float v = p + r;
                    float s = (v >= THETA) ? 1.0f : 0.0f;
                    r = DREF * (r - 2.0f * THETA * s);
                    oo[(size_t)j * OO] = s;
                }
            }
        }
    }
}

// ---------------------------------------------------------------------------
extern "C" void kernel_launch(void* const* d_in, const int* in_sizes, int n_in,
                              void* d_out, int out_size)
{
    const float* x  = (const float*)d_in[0];   // (64, 500, 1250)
    const float* W1 = (const float*)d_in[1];   // (512, 1250)
    const float* W2 = (const float*)d_in[2];   // (2, 512)
    float* out = (float*)d_out;                // (64, 500, 2)

    __half* w1h; cudaGetSymbolAddress((void**)&w1h, g_w1h);
    __half* u1;  cudaGetSymbolAddress((void**)&u1,  g_u1);
    float*  u2;  cudaGetSymbolAddress((void**)&u2,  g_u2);

    // zero the layer-2 membrane accumulator (graph-capturable memset node)
    cudaMemsetAsync(u2, 0, (size_t)MM * OO * sizeof(float));

    {
        long n = (long)HH * KP;
        cvt_w1_kernel<<<(unsigned)((n + 255) / 256), 256>>>(W1, w1h);
    }

    cudaFuncSetAttribute(gemm1_mma_kernel,
                         cudaFuncAttributeMaxDynamicSharedMemorySize, SMEM_GEMM);
    dim3 g1(HH / BN, MM / BM);                // (2, 500)
    gemm1_mma_kernel<<<g1, 256, SMEM_GEMM>>>(x, w1h, u1);

    dim3 g2(BV, HH / 128);                    // (64, 4)
    scan1_kernel<<<g2, 128>>>(u1, W2, u2);

    scan2_kernel<<<BV, 256>>>(u2, out);
}